// round 5
// baseline (speedup 1.0000x reference)
#include <cuda_runtime.h>
#include <cuda_bf16.h>
#include <math.h>

#define BATCH 8
#define DIM 96
#define HH 192
#define WW 192
#define NEXP 6
#define TOPK 3

typedef unsigned long long u64;

// ---------- packed f32x2 helpers (sm_103a) ----------
__device__ __forceinline__ u64 pk2(float lo, float hi) {
    u64 d; asm("mov.b64 %0, {%1, %2};" : "=l"(d) : "f"(lo), "f"(hi)); return d;
}
__device__ __forceinline__ void upk2(u64 d, float& lo, float& hi) {
    asm("mov.b64 {%0, %1}, %2;" : "=f"(lo), "=f"(hi) : "l"(d));
}
__device__ __forceinline__ u64 fma2(u64 a, u64 b, u64 c) {
    u64 d; asm("fma.rn.f32x2 %0, %1, %2, %3;" : "=l"(d) : "l"(a), "l"(b), "l"(c)); return d;
}
__device__ __forceinline__ u64 mul2(u64 a, u64 b) {
    u64 d; asm("mul.rn.f32x2 %0, %1, %2;" : "=l"(d) : "l"(a), "l"(b)); return d;
}
__device__ __forceinline__ u64 add2(u64 a, u64 b) {
    u64 d; asm("add.rn.f32x2 %0, %1, %2;" : "=l"(d) : "l"(a), "l"(b)); return d;
}

// ---------- device scratch ----------
__device__ float g_pooled[BATCH * DIM];
__device__ int   g_idx[BATCH * TOPK];
__device__ float g_w[BATCH * TOPK];

// ---------------------------------------------------------------
// Kernel A: per-(b,c) max+mean pooling over HxW
// ---------------------------------------------------------------
__global__ __launch_bounds__(256) void pool_kernel(const float* __restrict__ x) {
    int bc = blockIdx.x;
    const float4* p4 = reinterpret_cast<const float4*>(x + (size_t)bc * (HH * WW));
    float mx = -1e30f, sm = 0.f;
    for (int i = threadIdx.x; i < (HH * WW / 4); i += 256) {
        float4 v = p4[i];
        mx = fmaxf(mx, fmaxf(fmaxf(v.x, v.y), fmaxf(v.z, v.w)));
        sm += (v.x + v.y) + (v.z + v.w);
    }
#pragma unroll
    for (int o = 16; o; o >>= 1) {
        mx = fmaxf(mx, __shfl_xor_sync(0xffffffffu, mx, o));
        sm += __shfl_xor_sync(0xffffffffu, sm, o);
    }
    __shared__ float smx[8], ssm[8];
    int w = threadIdx.x >> 5, l = threadIdx.x & 31;
    if (l == 0) { smx[w] = mx; ssm[w] = sm; }
    __syncthreads();
    if (threadIdx.x == 0) {
        float M = smx[0], S = ssm[0];
#pragma unroll
        for (int i = 1; i < 8; i++) { M = fmaxf(M, smx[i]); S += ssm[i]; }
        g_pooled[bc] = M + S * (1.0f / (HH * WW));
    }
}

// ---------------------------------------------------------------
// Kernel B: gate
// ---------------------------------------------------------------
__global__ __launch_bounds__(64) void gate_kernel(const float* __restrict__ w_fc0,
                                                  const float* __restrict__ b_fc0,
                                                  const float* __restrict__ w_fc1,
                                                  const float* __restrict__ b_fc1) {
    __shared__ float sh_g[BATCH][NEXP], sh_nz[BATCH][NEXP];
    int t = threadIdx.x;
    if (t < BATCH * NEXP) {
        int b = t / NEXP, e = t - b * NEXP;
        const float* p = g_pooled + b * DIM;
        float d0 = b_fc0[e], d1 = b_fc1[e];
        for (int c = 0; c < DIM; c++) {
            float pv = p[c];
            d0 = fmaf(pv, w_fc0[e * DIM + c], d0);
            d1 = fmaf(pv, w_fc1[e * DIM + c], d1);
        }
        sh_g[b][e]  = (d1 >= 0.f) ? d1 : 0.2f * d1;
        sh_nz[b][e] = fmaxf(d0, 0.f) + log1pf(expf(-fabsf(d0)));
    }
    __syncthreads();
    if (t < BATCH) {
        int b = t;
        float g[NEXP], nz[NEXP];
#pragma unroll
        for (int e = 0; e < NEXP; e++) { g[e] = sh_g[b][e]; nz[e] = sh_nz[b][e]; }
        float mu = 0.f;
#pragma unroll
        for (int e = 0; e < NEXP; e++) mu += nz[e];
        mu *= (1.0f / NEXP);
        float var = 0.f;
#pragma unroll
        for (int e = 0; e < NEXP; e++) { float d = nz[e] - mu; var += d * d; }
        float sd = sqrtf(var / (NEXP - 1));
        float sc[NEXP];
#pragma unroll
        for (int e = 0; e < NEXP; e++) sc[e] = g[e] + (nz[e] - mu) / sd;

        bool used[NEXP] = {false, false, false, false, false, false};
        int idx[TOPK];
#pragma unroll
        for (int k = 0; k < TOPK; k++) {
            float best = -1e30f; int bi = 0;
#pragma unroll
            for (int e = 0; e < NEXP; e++)
                if (!used[e] && sc[e] > best) { best = sc[e]; bi = e; }
            used[bi] = true;
            idx[k] = bi;
        }
        float m = fmaxf(g[idx[0]], fmaxf(g[idx[1]], g[idx[2]]));
        float ex[TOPK], s = 0.f;
#pragma unroll
        for (int k = 0; k < TOPK; k++) { ex[k] = expf(g[idx[k]] - m); s += ex[k]; }
        float inv = 1.0f / s;
#pragma unroll
        for (int k = 0; k < TOPK; k++) {
            g_idx[b * TOPK + k] = idx[k];
            g_w[b * TOPK + k]   = ex[k] * inv;
        }
    }
}

// ---------------------------------------------------------------
// Kernel C: fused conv1 -> relu -> conv2 -> weighted sum (f32x2)
// ---------------------------------------------------------------
#define INW 196    // in_s row width (floats): col j at idx j+1
#define INW2 98
#define C1W 200    // c1_s row width (floats): col j at idx j+2
#define C1W2 100

struct P3 { u64 p0, p1, p2; };

// input tile window: col j at idx j+1 -> float2 loads at t, t+1
__device__ __forceinline__ P3 load3_in(const float2* row, int t) {
    float2 L = row[t];       // cols (2t-1, 2t)
    float2 R = row[t + 1];   // cols (2t+1, 2t+2)
    P3 r;
    r.p0 = pk2(L.x, L.y);
    r.p1 = pk2(L.y, R.x);
    r.p2 = pk2(R.x, R.y);
    return r;
}

// c1 window: col j at idx j+2 -> float2 loads at t, t+1, t+2
__device__ __forceinline__ P3 load3_c1(const float2* row, int t) {
    float2 L = row[t];       // cols (2t-2, 2t-1)
    float2 M = row[t + 1];   // cols (2t,   2t+1)
    float2 R = row[t + 2];   // cols (2t+2, 2t+3)
    P3 r;
    r.p0 = pk2(L.y, M.x);    // (2t-1, 2t)
    r.p1 = pk2(M.x, M.y);    // (2t,   2t+1)
    r.p2 = pk2(M.y, R.x);    // (2t+1, 2t+2)
    return r;
}

// conv1 + relu into c1_s. EDGE=true masks out-of-image rows to zero.
template <bool EDGE>
__device__ __forceinline__ void conv1_pass(const float2* in2, float* c1_s,
                                           const float* w1, float bias1,
                                           int t, int h0) {
    u64 K0 = pk2(w1[0], w1[0]), K1 = pk2(w1[1], w1[1]), K2 = pk2(w1[2], w1[2]);
    u64 K3 = pk2(w1[3], w1[3]), K4 = pk2(w1[4], w1[4]), K5 = pk2(w1[5], w1[5]);
    u64 K6 = pk2(w1[6], w1[6]), K7 = pk2(w1[7], w1[7]), K8 = pk2(w1[8], w1[8]);
    u64 B1 = pk2(bias1, bias1);

    P3 A = load3_in(in2 + 0 * INW2, t);
    P3 B = load3_in(in2 + 1 * INW2, t);
#pragma unroll
    for (int r = 0; r < 18; r++) {
        P3 C = load3_in(in2 + (r + 2) * INW2, t);
        u64 va = fma2(K0, A.p0, fma2(K1, A.p1, fma2(K2, A.p2, B1)));
        u64 vb = fma2(K3, B.p0, fma2(K4, B.p1, mul2(K5, B.p2)));
        u64 vc = fma2(K6, C.p0, fma2(K7, C.p1, mul2(K8, C.p2)));
        u64 v = add2(va, add2(vb, vc));
        float v0, v1; upk2(v, v0, v1);
        float r0 = fmaxf(v0, 0.f), r1 = fmaxf(v1, 0.f);
        if (EDGE) {
            const int hr = h0 + r - 1;
            const bool hok = (unsigned)hr < (unsigned)HH;
            r0 = hok ? r0 : 0.f;
            r1 = hok ? r1 : 0.f;
        }
        // col 2t at idx 2t+2 -> aligned float2 slot (t+1)
        reinterpret_cast<float2*>(c1_s + r * C1W)[t + 1] = make_float2(r0, r1);
        A = B; B = C;
    }
}

__global__ __launch_bounds__(96, 6) void moe_kernel(
    const float* __restrict__ x,
    const float* __restrict__ ew1, const float* __restrict__ eb1,
    const float* __restrict__ ew2, const float* __restrict__ eb2,
    float* __restrict__ out)
{
    const int t  = threadIdx.x;             // 0..95, column pair (2t, 2t+1)
    const int h0 = blockIdx.x * 16;
    const int c  = blockIdx.y;
    const int b  = blockIdx.z;
    const bool vedge = (h0 == 0) || (h0 + 16 == HH);

    // x tile: rows h0-2..h0+17 (20), col j at idx j+1 (halo cols zero)
    __shared__ __align__(16) float in_s[20 * INW];
    // relu(conv1) tile: rows h0-1..h0+16 (18), col j at idx j+2
    __shared__ __align__(16) float c1_s[18 * C1W];

    const float* xp = x + (size_t)(b * DIM + c) * (HH * WW);
    for (int idx = t; idx < 20 * INW; idx += 96) {
        int ri = idx / INW, ji = idx - ri * INW;
        int h = h0 - 2 + ri, w = ji - 1;
        float v = 0.f;
        if ((unsigned)h < (unsigned)HH && (unsigned)w < (unsigned)WW)
            v = xp[h * WW + w];
        in_s[idx] = v;
    }
    // c1 zero halo columns: col -1 (idx 1) and col 192 (idx 194); conv1 never writes them
    if (t < 18) { c1_s[t * C1W + 1] = 0.f; c1_s[t * C1W + 194] = 0.f; }

    u64 acc[16];
#pragma unroll
    for (int r = 0; r < 16; r++) acc[r] = 0ull;
    __syncthreads();

    const float2* in2 = reinterpret_cast<const float2*>(in_s);
    const float2* c12 = reinterpret_cast<const float2*>(c1_s);

    for (int ki = 0; ki < TOPK; ki++) {
        const int   e   = g_idx[b * TOPK + ki];
        const float cof = g_w[b * TOPK + ki];
        const float* w1 = ew1 + ((size_t)e * DIM + c) * 9;
        const float* w2 = ew2 + ((size_t)e * DIM + c) * 9;

        if (vedge)
            conv1_pass<true >(in2, c1_s, w1, eb1[e * DIM + c], t, h0);
        else
            conv1_pass<false>(in2, c1_s, w1, eb1[e * DIM + c], t, h0);
        __syncthreads();

        // ---- conv2 (weights pre-scaled by gate coeff), accumulate ----
        {
            u64 S0 = pk2(cof * w2[0], cof * w2[0]), S1 = pk2(cof * w2[1], cof * w2[1]);
            u64 S2 = pk2(cof * w2[2], cof * w2[2]), S3 = pk2(cof * w2[3], cof * w2[3]);
            u64 S4 = pk2(cof * w2[4], cof * w2[4]), S5 = pk2(cof * w2[5], cof * w2[5]);
            u64 S6 = pk2(cof * w2[6], cof * w2[6]), S7 = pk2(cof * w2[7], cof * w2[7]);
            u64 S8 = pk2(cof * w2[8], cof * w2[8]);
            float bbv = cof * eb2[e * DIM + c];
            u64 BB = pk2(bbv, bbv);

            P3 A = load3_c1(c12 + 0 * C1W2, t);
            P3 B = load3_c1(c12 + 1 * C1W2, t);
#pragma unroll
            for (int r = 0; r < 16; r++) {
                P3 C = load3_c1(c12 + (r + 2) * C1W2, t);
                u64 va = fma2(S0, A.p0, fma2(S1, A.p1, fma2(S2, A.p2, BB)));
                u64 vb = fma2(S3, B.p0, fma2(S4, B.p1, mul2(S5, B.p2)));
                u64 vc = fma2(S6, C.p0, fma2(S7, C.p1, mul2(S8, C.p2)));
                acc[r] = add2(acc[r], add2(va, add2(vb, vc)));
                A = B; B = C;
            }
        }
        __syncthreads();
    }

    float* op = out + (size_t)(b * DIM + c) * (HH * WW) + h0 * WW + 2 * t;
#pragma unroll
    for (int r = 0; r < 16; r++) {
        float o0, o1; upk2(acc[r], o0, o1);
        reinterpret_cast<float2*>(op + r * WW)[0] = make_float2(o0, o1);
    }
}

// ---------------------------------------------------------------
extern "C" void kernel_launch(void* const* d_in, const int* in_sizes, int n_in,
                              void* d_out, int out_size) {
    const float* x     = (const float*)d_in[0];
    const float* w_fc0 = (const float*)d_in[1];
    const float* b_fc0 = (const float*)d_in[2];
    const float* w_fc1 = (const float*)d_in[3];
    const float* b_fc1 = (const float*)d_in[4];
    const float* ew1   = (const float*)d_in[5];
    const float* eb1   = (const float*)d_in[6];
    const float* ew2   = (const float*)d_in[7];
    const float* eb2   = (const float*)d_in[8];
    float* out = (float*)d_out;

    pool_kernel<<<BATCH * DIM, 256>>>(x);
    gate_kernel<<<1, 64>>>(w_fc0, b_fc0, w_fc1, b_fc1);
    dim3 grid(HH / 16, DIM, BATCH);
    moe_kernel<<<grid, 96>>>(x, ew1, eb1, ew2, eb2, out);
}